// round 13
// baseline (speedup 1.0000x reference)
#include <cuda_runtime.h>

// ---------------- problem constants ----------------
#define BB   4
#define NPG  2048        // coarse nodes per graph
#define MM   65536       // skip nodes
#define MPG  16384
#define EE   131072      // edges
#define EPG  32768
#define TT   16          // tokens per graph
#define FIN  16
#define GDIM 1024
#define EMB  64
#define NH   4
#define HD   16
#define CI   32
#define PDIM 67          // 3 + 64
#define PSTR 68          // padded pseudo vector length (17 float4)
#define P2N  34          // p-pairs
#define SUBQ 544         // float4 per 32-edge sub-block (17 * 32)

typedef unsigned long long ull;

// ---------------- device scratch (no cudaMalloc allowed) ----------------
// pseudo stored sub-block transposed: [e/32][ q*32 + (e&31) ] float4, q = p-pair-pair 0..16
__device__ __align__(16) float d_pseudo[EE * PSTR];   // 35.6 MB
__device__ float d_h0[MM * CI];
__device__ float d_h1[MM * CI];
__device__ float d_aggr[MM * CI];
__device__ int   d_cnt[MM];
// weight layout per layer: ull index ((p2*8 + b4)*CO + o)*4 + i  -> float pair (2*p2, 2*p2+1)
__device__ __align__(16) float d_Wt0[P2N * 1024 * 2];
__device__ __align__(16) float d_Wt1[P2N * 1024 * 2];
__device__ __align__(16) float d_Wt2[P2N * 512 * 2];
__device__ float d_A[EMB * 3];
__device__ float d_cc[EMB];
__device__ float d_K2[BB * TT * EMB];
__device__ float d_V2[BB * TT * EMB];
__device__ float d_U[BB * NH * TT * 3];
__device__ float d_s0[BB * NH * TT];
__device__ float d_OV[BB * NH * TT * EMB];

// ---------------- packed f32x2 helpers ----------------
__device__ __forceinline__ void fma2(ull& d, ull a, ull b) {
    asm("fma.rn.f32x2 %0, %1, %2, %0;" : "+l"(d) : "l"(a), "l"(b));
}
__device__ __forceinline__ float red2(ull v) {
    float lo, hi;
    asm("mov.b64 {%0, %1}, %2;" : "=f"(lo), "=f"(hi) : "l"(v));
    return lo + hi;
}

// ---------------- setup kernel: K2/V2 tokens + A/cc + weight re-layout, one launch ----------------
#define TRW0 (P2N * 1024)          // ull count, layer 0
#define TRW1 (P2N * 1024)
#define TRW2 (P2N * 512)
#define TRBLK ((TRW0 + TRW1 + TRW2) / 256)   // 340 blocks

__global__ void setup_kernel(const float* __restrict__ gt,
                             const float* __restrict__ Wk_w, const float* __restrict__ Wk_b,
                             const float* __restrict__ Wv_w, const float* __restrict__ Wv_b,
                             const float* __restrict__ ipw, const float* __restrict__ ipb,
                             const float* __restrict__ Wq_w, const float* __restrict__ Wq_b,
                             const float* __restrict__ nw0, const float* __restrict__ nw1,
                             const float* __restrict__ nw2) {
    int bid = blockIdx.x;
    if (bid < BB * TT) {
        // token projections, 4-way split over GDIM
        __shared__ float pK[4][EMB], pV[4][EMB];
        __shared__ float Kt[EMB], Vt[EMB];
        int bt = bid, tloc = bt % TT;
        int q = threadIdx.x >> 6, j = threadIdx.x & 63;
        const float* g  = gt + (size_t)bt * GDIM + q * 256;
        const float* wk = Wk_w + (size_t)j * GDIM + q * 256;
        const float* wv = Wv_w + (size_t)j * GDIM + q * 256;
        float sk = 0.f, sv = 0.f;
        for (int i = 0; i < 256; i += 4) {
            float4 gv = *(const float4*)(g + i);
            float4 k4 = *(const float4*)(wk + i);
            float4 v4 = *(const float4*)(wv + i);
            sk += gv.x * k4.x + gv.y * k4.y + gv.z * k4.z + gv.w * k4.w;
            sv += gv.x * v4.x + gv.y * v4.y + gv.z * v4.z + gv.w * v4.w;
        }
        pK[q][j] = sk; pV[q][j] = sv;
        __syncthreads();
        if (q == 0) {
            int i2 = j & ~1;
            float div = expf(-(float)i2 * (9.210340371976184f / (float)EMB));
            float ang = (float)tloc * div;
            float pe = (j & 1) ? cosf(ang) : sinf(ang);
            Kt[j] = pK[0][j] + pK[1][j] + pK[2][j] + pK[3][j] + Wk_b[j] + pe;
            Vt[j] = pV[0][j] + pV[1][j] + pV[2][j] + pV[3][j] + Wv_b[j] + pe;
        }
        __syncthreads();
        if (q == 0) {
            const float* wkr = ipw + (size_t)(EMB + j) * EMB;
            const float* wvr = ipw + (size_t)(2 * EMB + j) * EMB;
            float s2k = ipb[EMB + j], s2v = ipb[2 * EMB + j];
            for (int i = 0; i < EMB; i++) { s2k += Kt[i] * wkr[i]; s2v += Vt[i] * wvr[i]; }
            d_K2[bt * EMB + j] = s2k;
            d_V2[bt * EMB + j] = s2v;
        }
        return;
    }
    if (bid == BB * TT) {
        // A = wq @ Wq_w, cc = bq + wq @ Wq_b
        int t = threadIdx.x;
        for (int idx = t; idx < EMB * 3; idx += blockDim.x) {
            int j = idx / 3, p = idx % 3;
            float s = 0.f;
            for (int i = 0; i < EMB; i++) s += ipw[j * EMB + i] * Wq_w[i * 3 + p];
            d_A[idx] = s;
        }
        for (int j = t; j < EMB; j += blockDim.x) {
            float s = ipb[j];
            for (int i = 0; i < EMB; i++) s += ipw[j * EMB + i] * Wq_b[i];
            d_cc[j] = s;
        }
        return;
    }
    // weight re-layout
    int u = (bid - (BB * TT + 1)) * 256 + threadIdx.x;
    const float* nw; float* wt; int CO;
    if (u < TRW0)              { nw = nw0; wt = d_Wt0; CO = 32; }
    else if (u < TRW0 + TRW1)  { nw = nw1; wt = d_Wt1; CO = 32; u -= TRW0; }
    else                       { nw = nw2; wt = d_Wt2; CO = 16; u -= TRW0 + TRW1; }
    int i  = u & 3;
    int o  = (u >> 2) % CO;
    int b4 = ((u >> 2) / CO) & 7;
    int p2 = u / (32 * CO);
    int j  = (b4 * 4 + i) * CO + o;
    float lo = nw[j * PDIM + 2 * p2];
    float hi = (2 * p2 + 1 < PDIM) ? nw[j * PDIM + 2 * p2 + 1] : 0.f;
    wt[(size_t)u * 2]     = lo;
    wt[(size_t)u * 2 + 1] = hi;
}

// ---------------- mid kernel: s3 (blocks 0..3) + knn (blocks 4..) ----------------
__global__ void mid_kernel(const float* __restrict__ x, const float* __restrict__ pos,
                           const float* __restrict__ x_skip, const float* __restrict__ pos_skip,
                           const float* __restrict__ out_w) {
    __shared__ __align__(16) float4 sh4[NPG];   // {x, y, z, -0.5*|c|^2}
    int bid = blockIdx.x;
    if (bid < BB) {
        int b = bid, t = threadIdx.x;
        for (int idx = t; idx < NH * TT * 3; idx += blockDim.x) {
            int p = idx % 3; int ht = idx / 3; int h = ht / TT, tt = ht % TT;
            float s = 0.f;
            for (int d = 0; d < HD; d++)
                s += d_A[(h * HD + d) * 3 + p] * d_K2[(b * TT + tt) * EMB + h * HD + d];
            d_U[b * NH * TT * 3 + idx] = 0.25f * s;
        }
        for (int idx = t; idx < NH * TT; idx += blockDim.x) {
            int h = idx / TT, tt = idx % TT;
            float s = 0.f;
            for (int d = 0; d < HD; d++)
                s += d_cc[h * HD + d] * d_K2[(b * TT + tt) * EMB + h * HD + d];
            d_s0[b * NH * TT + idx] = 0.25f * s;
        }
        for (int idx = t; idx < NH * TT * EMB; idx += blockDim.x) {
            int j = idx % EMB; int ht = idx / EMB; int h = ht / TT, tt = ht % TT;
            float s = 0.f;
            for (int d = 0; d < HD; d++)
                s += out_w[j * EMB + h * HD + d] * d_V2[(b * TT + tt) * EMB + h * HD + d];
            d_OV[b * NH * TT * EMB + idx] = s;
        }
        return;
    }
    // ---- knn part: 128 threads/block, one skip node per thread ----
    int m = (bid - BB) * 128 + threadIdx.x;
    int b = m / MPG;
    const float* cp = pos + (size_t)b * NPG * 3;
    for (int j = threadIdx.x; j < NPG; j += 128) {
        float X = cp[j * 3], Y = cp[j * 3 + 1], Z = cp[j * 3 + 2];
        sh4[j] = make_float4(X, Y, Z, -0.5f * (X * X + Y * Y + Z * Z));
    }
    __syncthreads();

    // fold in: zero degree counter + layer-0 aggregation buffer
    d_cnt[m] = 0;
    float4 z4 = make_float4(0.f, 0.f, 0.f, 0.f);
    #pragma unroll
    for (int q = 0; q < CI / 4; q++) ((float4*)(d_aggr + (size_t)m * CI))[q] = z4;

    float px = pos_skip[m * 3], py = pos_skip[m * 3 + 1], pz = pos_skip[m * 3 + 2];
    float ps2 = px * px + py * py + pz * pz;
    // maximize s = dot - 0.5*|c|^2  (equiv. minimize squared distance)
    float b0 = -1e30f, b1 = -1e30f, b2 = -1e30f;
    int i0 = 0, i1 = 0, i2 = 0;
    #pragma unroll 4
    for (int j = 0; j < NPG; j++) {
        float4 c = sh4[j];
        float s = fmaf(px, c.x, fmaf(py, c.y, fmaf(pz, c.z, c.w)));
        if (s > b2) {
            if (s > b1) {
                b2 = b1; i2 = i1;
                if (s > b0) { b1 = b0; i1 = i0; b0 = s; i0 = j; }
                else        { b1 = s;  i1 = j; }
            } else { b2 = s; i2 = j; }
        }
    }
    float d0 = fmaf(-2.f, b0, ps2);
    float d1 = fmaf(-2.f, b1, ps2);
    float d2 = fmaf(-2.f, b2, ps2);
    float w0 = 1.f / fmaxf(d0, 1e-16f);
    float w1 = 1.f / fmaxf(d1, 1e-16f);
    float w2 = 1.f / fmaxf(d2, 1e-16f);
    float inv = 1.f / (w0 + w1 + w2);
    const float* x0 = x + (size_t)(b * NPG + i0) * FIN;
    const float* x1 = x + (size_t)(b * NPG + i1) * FIN;
    const float* x2 = x + (size_t)(b * NPG + i2) * FIN;
    const float* xs = x_skip + (size_t)m * FIN;
    float* h = d_h0 + (size_t)m * CI;
    #pragma unroll
    for (int f = 0; f < FIN; f++) {
        h[f]       = (w0 * x0[f] + w1 * x1[f] + w2 * x2[f]) * inv;
        h[FIN + f] = xs[f];
    }
}

// ---------------- degree ----------------
__global__ void deg_kernel(const int* __restrict__ ei) {
    int e = blockIdx.x * blockDim.x + threadIdx.x;
    if (e < EE) atomicAdd(&d_cnt[ei[EE + e]], 1);
}

// ---------------- stage B: per-edge attention -> sub-block-transposed pseudo ----------------
__global__ void attn_kernel(const int* __restrict__ ei, const float* __restrict__ pos_skip,
                            const float* __restrict__ out_b) {
    __shared__ float4 sOV4[NH * TT * EMB / 4];
    __shared__ float sU[NH * TT * 3], sS0[NH * TT], sOB[EMB];
    int e = blockIdx.x * blockDim.x + threadIdx.x;
    int b = blockIdx.x / (EPG / 256);
    float* sOV = (float*)sOV4;
    for (int i = threadIdx.x; i < NH * TT * EMB; i += 256) sOV[i] = d_OV[b * NH * TT * EMB + i];
    for (int i = threadIdx.x; i < NH * TT * 3;  i += 256) sU[i]  = d_U[b * NH * TT * 3 + i];
    for (int i = threadIdx.x; i < NH * TT;      i += 256) sS0[i] = d_s0[b * NH * TT + i];
    for (int i = threadIdx.x; i < EMB;          i += 256) sOB[i] = out_b[i];
    __syncthreads();
    int s = ei[e], d = ei[EE + e];
    float sx = pos_skip[s * 3], sy = pos_skip[s * 3 + 1], sz = pos_skip[s * 3 + 2];
    float dx = pos_skip[d * 3], dy = pos_skip[d * 3 + 1], dz = pos_skip[d * 3 + 2];
    float epx = 0.5f * (dx + sx), epy = 0.5f * (dy + sy), epz = 0.5f * (dz + sz);
    float v[PSTR];
    v[0] = dx - sx; v[1] = dy - sy; v[2] = dz - sz;
    #pragma unroll
    for (int j = 0; j < EMB; j++) v[3 + j] = sOB[j];
    v[67] = 0.f;
    #pragma unroll
    for (int h = 0; h < NH; h++) {
        float sc[TT];
        float mx = -1e30f;
        #pragma unroll
        for (int t = 0; t < TT; t++) {
            int ht = h * TT + t;
            sc[t] = sS0[ht] + epx * sU[ht * 3] + epy * sU[ht * 3 + 1] + epz * sU[ht * 3 + 2];
            mx = fmaxf(mx, sc[t]);
        }
        float se = 0.f;
        #pragma unroll
        for (int t = 0; t < TT; t++) { sc[t] = __expf(sc[t] - mx); se += sc[t]; }
        float inv = 1.f / se;
        #pragma unroll
        for (int t = 0; t < TT; t++) {
            float a = sc[t] * inv;
            const float4* row = sOV4 + (h * TT + t) * (EMB / 4);
            #pragma unroll
            for (int q = 0; q < EMB / 4; q++) {
                float4 vv = row[q];
                v[3 + 4 * q]     += a * vv.x;
                v[3 + 4 * q + 1] += a * vv.y;
                v[3 + 4 * q + 2] += a * vv.z;
                v[3 + 4 * q + 3] += a * vv.w;
            }
        }
    }
    // sub-block-transposed write: dest float4 index = (e/32)*544 + q*32 + (e%32)
    float4* dst = (float4*)d_pseudo + (size_t)(e >> 5) * SUBQ + (e & 31);
    #pragma unroll
    for (int q = 0; q < 17; q++)
        dst[q * 32] = make_float4(v[4 * q], v[4 * q + 1], v[4 * q + 2], v[4 * q + 3]);
}

// ---------------- stage C: fused edge MLP (GE=4, 3 blocks/SM) ----------------
template <int CO>
__global__ void __launch_bounds__(256, 3)
edge_kernel(int layer, const int* __restrict__ ei, const float* __restrict__ nb) {
    constexpr int NT = 256;
    constexpr int WO = CO / 8;            // warps along o
    constexpr int NSLAB = 8 / WO;         // 16-edge slabs per block
    constexpr int BE = 16 * NSLAB;        // edges per block (CO=32: 32, CO=16: 64)
    constexpr int NSUB = BE / 32;         // 32-edge pseudo sub-blocks
    __shared__ __align__(16) float4 ps_s[NSUB * SUBQ];
    __shared__ float hs_s[BE * 33];
    __shared__ float nb_s[CI * CO];
    __shared__ int   dst_s[BE];

    const ull* WtU = (const ull*)((layer == 0) ? d_Wt0 : (layer == 1) ? d_Wt1 : d_Wt2);
    const float* hin = (layer == 1) ? d_h1 : d_h0;

    int e0 = blockIdx.x * BE;
    const float4* pg = (const float4*)d_pseudo + (size_t)(e0 >> 5) * SUBQ;
    for (int idx = threadIdx.x; idx < NSUB * SUBQ; idx += NT) ps_s[idx] = pg[idx];
    for (int idx = threadIdx.x; idx < BE * CI; idx += NT) {
        int el = idx >> 5, i = idx & 31;
        hs_s[el * 33 + i] = hin[(size_t)ei[e0 + el] * CI + i];
    }
    for (int idx = threadIdx.x; idx < BE; idx += NT) dst_s[idx] = ei[EE + e0 + idx];
    for (int idx = threadIdx.x; idx < CI * CO; idx += NT) nb_s[idx] = nb[idx];
    __syncthreads();

    int l = threadIdx.x & 31, w = threadIdx.x >> 5;
    int o  = (w % WO) * 8 + (l & 7);
    int eh = w / WO;                 // 16-edge slab 0..NSLAB-1
    int g  = l >> 3;                 // 0..3
    // thread's edges: el = eh*16 + k*4 + g, k = 0..3
    int sub = eh >> 1, ehh = eh & 1;
    const ulonglong2* ps2 = (const ulonglong2*)(ps_s + sub * SUBQ);
    int abase = ehh * 16 + g;        // ps chunk = q*32 + abase + k*4
    int hbase = (eh * 16 + g) * 33;  // hs index (k, ic) = hbase + 132*k + ic
    float msg[4] = {0.f, 0.f, 0.f, 0.f};

    #pragma unroll 1
    for (int b4 = 0; b4 < CI / 4; b4++) {
        ull z2[4][4];
        #pragma unroll
        for (int i = 0; i < 4; i++)
            #pragma unroll
            for (int k = 0; k < 4; k++) z2[i][k] = 0ull;

        // weight chunk base for (b4, o); per-p2 stride = 16*CO ulonglong2
        const ulonglong2* wpe = (const ulonglong2*)(WtU + (size_t)(b4 * CO + o) * 4);
        #pragma unroll 2
        for (int p2g = 0; p2g < 17; p2g++) {
            ulonglong2 wa0 = wpe[(size_t)p2g * 32 * CO];
            ulonglong2 wa1 = wpe[(size_t)p2g * 32 * CO + 1];
            ulonglong2 wb0 = wpe[(size_t)p2g * 32 * CO + 16 * CO];
            ulonglong2 wb1 = wpe[(size_t)p2g * 32 * CO + 16 * CO + 1];
            ull wa[4] = {wa0.x, wa0.y, wa1.x, wa1.y};
            ull wb[4] = {wb0.x, wb0.y, wb1.x, wb1.y};
            #pragma unroll
            for (int k = 0; k < 4; k++) {
                // one LDS.128: {a_even, a_odd} for edge (eh, k*4+g)
                ulonglong2 a = ps2[p2g * 32 + abase + k * 4];
                #pragma unroll
                for (int i = 0; i < 4; i++) {
                    fma2(z2[i][k], a.x, wa[i]);
                    fma2(z2[i][k], a.y, wb[i]);
                }
            }
        }
        #pragma unroll
        for (int i = 0; i < 4; i++) {
            float nbv = nb_s[(b4 * 4 + i) * CO + o];
            #pragma unroll
            for (int k = 0; k < 4; k++) {
                float z = red2(z2[i][k]) + nbv;
                msg[k] = fmaf(hs_s[hbase + 132 * k + b4 * 4 + i], fmaxf(z, 0.f), msg[k]);
            }
        }
    }
    #pragma unroll
    for (int k = 0; k < 4; k++)
        atomicAdd(&d_aggr[(size_t)dst_s[eh * 16 + k * 4 + g] * CO + o], msg[k]);
}

// node update: h_out = relu(aggr/cnt + h_in @ root + bias); re-zeroes aggr for next layer
template <int CO>
__global__ void node_kernel(int layer, const float* __restrict__ root,
                            const float* __restrict__ bias, float* __restrict__ finalout,
                            int out_size) {
    __shared__ float4 root4[CI * CO / 4];
    __shared__ float  bias_s[CO];
    for (int i = threadIdx.x; i < CI * CO / 4; i += blockDim.x) root4[i] = ((const float4*)root)[i];
    for (int i = threadIdx.x; i < CO; i += blockDim.x) bias_s[i] = bias[i];
    __syncthreads();

    const float* hin = (layer == 1) ? d_h1 : d_h0;
    int v = blockIdx.x * blockDim.x + threadIdx.x;
    float inv = 1.f / (float)max(d_cnt[v], 1);

    float4 acc[CO / 4];
    #pragma unroll
    for (int q = 0; q < CO / 4; q++) {
        float4 ag = ((const float4*)(d_aggr + (size_t)v * CO))[q];
        acc[q].x = bias_s[4 * q]     + ag.x * inv;
        acc[q].y = bias_s[4 * q + 1] + ag.y * inv;
        acc[q].z = bias_s[4 * q + 2] + ag.z * inv;
        acc[q].w = bias_s[4 * q + 3] + ag.w * inv;
    }
    if (layer < 2) {
        float4 z4 = make_float4(0.f, 0.f, 0.f, 0.f);
        #pragma unroll
        for (int q = 0; q < CI / 4; q++) ((float4*)(d_aggr + (size_t)v * CI))[q] = z4;
    }
    float hv[CI];
    #pragma unroll
    for (int q = 0; q < CI / 4; q++) {
        float4 t = ((const float4*)(hin + (size_t)v * CI))[q];
        hv[4 * q] = t.x; hv[4 * q + 1] = t.y; hv[4 * q + 2] = t.z; hv[4 * q + 3] = t.w;
    }
    #pragma unroll
    for (int i = 0; i < CI; i++) {
        #pragma unroll
        for (int q = 0; q < CO / 4; q++) {
            float4 r = root4[i * (CO / 4) + q];
            acc[q].x = fmaf(hv[i], r.x, acc[q].x);
            acc[q].y = fmaf(hv[i], r.y, acc[q].y);
            acc[q].z = fmaf(hv[i], r.z, acc[q].z);
            acc[q].w = fmaf(hv[i], r.w, acc[q].w);
        }
    }
    float* hout = (layer == 0) ? d_h1 : (layer == 1) ? d_h0 : finalout;
    #pragma unroll
    for (int q = 0; q < CO / 4; q++) {
        float4 r;
        r.x = fmaxf(acc[q].x, 0.f); r.y = fmaxf(acc[q].y, 0.f);
        r.z = fmaxf(acc[q].z, 0.f); r.w = fmaxf(acc[q].w, 0.f);
        if (layer == 2) {
            int ofs = v * CO + 4 * q;
            if (ofs + 4 <= out_size) ((float4*)(hout + ofs))[0] = r;
        } else {
            ((float4*)(hout + (size_t)v * CO))[q] = r;
        }
    }
}

// remaining reference outputs (pos_skip, batch_skip) if the harness expects them
__global__ void tail_kernel(const float* __restrict__ pos_skip, const int* __restrict__ batch_skip,
                            float* __restrict__ out, int out_size) {
    int i = blockIdx.x * blockDim.x + threadIdx.x;
    int base = MM * 16;
    if (i < MM * 3 && base + i < out_size) out[base + i] = pos_skip[i];
    int base2 = base + MM * 3;
    if (i < MM && base2 + i < out_size) out[base2 + i] = (float)batch_skip[i];
}

// ---------------- launch ----------------
extern "C" void kernel_launch(void* const* d_in, const int* in_sizes, int n_in,
                              void* d_out, int out_size) {
    const float* x        = (const float*)d_in[0];
    const float* pos      = (const float*)d_in[1];
    const float* x_skip   = (const float*)d_in[3];
    const float* pos_skip = (const float*)d_in[4];
    const int*   batch_sk = (const int*)  d_in[5];
    const int*   ei       = (const int*)  d_in[6];
    const float* gt       = (const float*)d_in[7];
    const float* Wq_w = (const float*)d_in[8];   const float* Wq_b = (const float*)d_in[9];
    const float* Wk_w = (const float*)d_in[10];  const float* Wk_b = (const float*)d_in[11];
    const float* Wv_w = (const float*)d_in[12];  const float* Wv_b = (const float*)d_in[13];
    const float* ipw  = (const float*)d_in[14];  const float* ipb  = (const float*)d_in[15];
    const float* ow   = (const float*)d_in[16];  const float* ob   = (const float*)d_in[17];
    const float* nw0 = (const float*)d_in[18]; const float* nb0 = (const float*)d_in[19];
    const float* rt0 = (const float*)d_in[20]; const float* bs0 = (const float*)d_in[21];
    const float* nw1 = (const float*)d_in[22]; const float* nb1 = (const float*)d_in[23];
    const float* rt1 = (const float*)d_in[24]; const float* bs1 = (const float*)d_in[25];
    const float* nw2 = (const float*)d_in[26]; const float* nb2 = (const float*)d_in[27];
    const float* rt2 = (const float*)d_in[28]; const float* bs2 = (const float*)d_in[29];
    float* out = (float*)d_out;

    // launch #1: tokens + A/cc + weight re-layout
    setup_kernel<<<BB * TT + 1 + TRBLK, 256>>>(gt, Wk_w, Wk_b, Wv_w, Wv_b, ipw, ipb,
                                               Wq_w, Wq_b, nw0, nw1, nw2);
    // launch #2: s3 + knn (also zeroes cnt + aggr)
    mid_kernel<<<BB + MM / 128, 128>>>(x, pos, x_skip, pos_skip, ow);
    // launch #3: attention -> sub-block-transposed pseudo
    attn_kernel<<<EE / 256, 256>>>(ei, pos_skip, ob);

    // launch #4: dominant kernel (targeted ncu capture slot)
    edge_kernel<32><<<EE / 32, 256>>>(0, ei, nb0);
    deg_kernel<<<EE / 256, 256>>>(ei);
    node_kernel<32><<<MM / 256, 256>>>(0, rt0, bs0, nullptr, 0);   // zeroes aggr for L1
    edge_kernel<32><<<EE / 32, 256>>>(1, ei, nb1);
    node_kernel<32><<<MM / 256, 256>>>(1, rt1, bs1, nullptr, 0);   // zeroes aggr for L2
    edge_kernel<16><<<EE / 64, 256>>>(2, ei, nb2);
    node_kernel<16><<<MM / 256, 256>>>(2, rt2, bs2, out, out_size);

    tail_kernel<<<(MM * 3 + 255) / 256, 256>>>(pos_skip, batch_sk, out, out_size);
}

// round 15
// speedup vs baseline: 1.8044x; 1.8044x over previous
#include <cuda_runtime.h>
#include <cuda_bf16.h>

// ---------------- problem constants ----------------
#define BB   4
#define NPG  2048
#define MM   65536
#define MPG  16384
#define EE   131072
#define EPG  32768
#define TT   16
#define FIN  16
#define GDIM 1024
#define EMB  64
#define NH   4
#define HD   16
#define CI   32
#define PDIM 67
#define PROW 68          // pseudo row stride (floats)
#define KP   240         // split-K (3 x 80)
#define ASTR 496         // smem row stride bytes (conflict-free for ldmatrix)

typedef unsigned long long ull;
typedef unsigned int u32;

__device__ __forceinline__ u32 smem_u32(const void* p) {
    u32 a;
    asm("{ .reg .u64 t; cvta.to.shared.u64 t, %1; cvt.u32.u64 %0, t; }" : "=r"(a) : "l"(p));
    return a;
}
__device__ __forceinline__ void ldsm_x4(u32& r0, u32& r1, u32& r2, u32& r3, u32 a) {
    asm volatile("ldmatrix.sync.aligned.m8n8.x4.shared.b16 {%0,%1,%2,%3}, [%4];"
        : "=r"(r0), "=r"(r1), "=r"(r2), "=r"(r3) : "r"(a));
}
__device__ __forceinline__ void ldsm_x2(u32& r0, u32& r1, u32 a) {
    asm volatile("ldmatrix.sync.aligned.m8n8.x2.shared.b16 {%0,%1}, [%2];"
        : "=r"(r0), "=r"(r1) : "r"(a));
}
__device__ __forceinline__ void mma_bf16(float* d, u32 a0, u32 a1, u32 a2, u32 a3, u32 b0, u32 b1) {
    asm volatile("mma.sync.aligned.m16n8k16.row.col.f32.bf16.bf16.f32 "
        "{%0,%1,%2,%3}, {%4,%5,%6,%7}, {%8,%9}, {%0,%1,%2,%3};"
        : "+f"(d[0]), "+f"(d[1]), "+f"(d[2]), "+f"(d[3])
        : "r"(a0), "r"(a1), "r"(a2), "r"(a3), "r"(b0), "r"(b1));
}
__device__ __forceinline__ u32 pack_bf16(__nv_bfloat16 lo, __nv_bfloat16 hi) {
    return ((u32)__bfloat16_as_ushort(hi) << 16) | (u32)__bfloat16_as_ushort(lo);
}

// ---------------- device scratch ----------------
__device__ __align__(16) float d_pseudo[EE * PROW];
__device__ float d_h0[MM * CI];
__device__ float d_h1[MM * CI];
__device__ float d_aggr[MM * CI];
__device__ int   d_cnt[MM];
// bf16 split-K weight images: [j][240], j-major, k contiguous
__device__ __align__(16) __nv_bfloat16 d_Bw0[1024 * KP];
__device__ __align__(16) __nv_bfloat16 d_Bw1[1024 * KP];
__device__ __align__(16) __nv_bfloat16 d_Bw2[512 * KP];
__device__ float d_A[EMB * 3];
__device__ float d_cc[EMB];
__device__ float d_K2[BB * TT * EMB];
__device__ float d_V2[BB * TT * EMB];
__device__ float d_U[BB * NH * TT * 3];
__device__ float d_s0[BB * NH * TT];
__device__ float d_OV[BB * NH * TT * EMB];

// ---------------- setup: tokens + A/cc + B weight images ----------------
#define BWTOT ((1024 + 1024 + 512) * KP)    // 614400
#define BWBLK (BWTOT / 256)                 // 2400

__global__ void setup_kernel(const float* __restrict__ gt,
                             const float* __restrict__ Wk_w, const float* __restrict__ Wk_b,
                             const float* __restrict__ Wv_w, const float* __restrict__ Wv_b,
                             const float* __restrict__ ipw, const float* __restrict__ ipb,
                             const float* __restrict__ Wq_w, const float* __restrict__ Wq_b,
                             const float* __restrict__ nw0, const float* __restrict__ nw1,
                             const float* __restrict__ nw2) {
    int bid = blockIdx.x;
    if (bid < BB * TT) {
        __shared__ float pK[4][EMB], pV[4][EMB];
        __shared__ float Kt[EMB], Vt[EMB];
        int bt = bid, tloc = bt % TT;
        int q = threadIdx.x >> 6, j = threadIdx.x & 63;
        const float* g  = gt + (size_t)bt * GDIM + q * 256;
        const float* wk = Wk_w + (size_t)j * GDIM + q * 256;
        const float* wv = Wv_w + (size_t)j * GDIM + q * 256;
        float sk = 0.f, sv = 0.f;
        for (int i = 0; i < 256; i += 4) {
            float4 gv = *(const float4*)(g + i);
            float4 k4 = *(const float4*)(wk + i);
            float4 v4 = *(const float4*)(wv + i);
            sk += gv.x * k4.x + gv.y * k4.y + gv.z * k4.z + gv.w * k4.w;
            sv += gv.x * v4.x + gv.y * v4.y + gv.z * v4.z + gv.w * v4.w;
        }
        pK[q][j] = sk; pV[q][j] = sv;
        __syncthreads();
        if (q == 0) {
            int i2 = j & ~1;
            float div = expf(-(float)i2 * (9.210340371976184f / (float)EMB));
            float ang = (float)tloc * div;
            float pe = (j & 1) ? cosf(ang) : sinf(ang);
            Kt[j] = pK[0][j] + pK[1][j] + pK[2][j] + pK[3][j] + Wk_b[j] + pe;
            Vt[j] = pV[0][j] + pV[1][j] + pV[2][j] + pV[3][j] + Wv_b[j] + pe;
        }
        __syncthreads();
        if (q == 0) {
            const float* wkr = ipw + (size_t)(EMB + j) * EMB;
            const float* wvr = ipw + (size_t)(2 * EMB + j) * EMB;
            float s2k = ipb[EMB + j], s2v = ipb[2 * EMB + j];
            for (int i = 0; i < EMB; i++) { s2k += Kt[i] * wkr[i]; s2v += Vt[i] * wvr[i]; }
            d_K2[bt * EMB + j] = s2k;
            d_V2[bt * EMB + j] = s2v;
        }
        return;
    }
    if (bid == BB * TT) {
        int t = threadIdx.x;
        for (int idx = t; idx < EMB * 3; idx += blockDim.x) {
            int j = idx / 3, p = idx % 3;
            float s = 0.f;
            for (int i = 0; i < EMB; i++) s += ipw[j * EMB + i] * Wq_w[i * 3 + p];
            d_A[idx] = s;
        }
        for (int j = t; j < EMB; j += blockDim.x) {
            float s = ipb[j];
            for (int i = 0; i < EMB; i++) s += ipw[j * EMB + i] * Wq_b[i];
            d_cc[j] = s;
        }
        return;
    }
    // B image: k<80 -> hi, 80..159 -> hi, 160..239 -> lo
    int u = (bid - (BB * TT + 1)) * 256 + threadIdx.x;
    const float* nw; __nv_bfloat16* Bw; int rel;
    if (u < 1024 * KP)            { nw = nw0; Bw = d_Bw0; rel = u; }
    else if (u < 2048 * KP)       { nw = nw1; Bw = d_Bw1; rel = u - 1024 * KP; }
    else if (u < 2560 * KP)       { nw = nw2; Bw = d_Bw2; rel = u - 2048 * KP; }
    else return;
    int j = rel / KP, k = rel - j * KP;
    int seg = k / 80, c = k - seg * 80;
    float w = (c < PDIM) ? nw[j * PDIM + c] : 0.f;
    __nv_bfloat16 hi = __float2bfloat16(w);
    __nv_bfloat16 lo = __float2bfloat16(w - __bfloat162float(hi));
    Bw[rel] = (seg == 2) ? lo : hi;
}

// ---------------- mid: s3 (blocks 0..3) + knn (rest) ----------------
__global__ void mid_kernel(const float* __restrict__ x, const float* __restrict__ pos,
                           const float* __restrict__ x_skip, const float* __restrict__ pos_skip,
                           const float* __restrict__ out_w) {
    __shared__ __align__(16) float4 sh4[NPG];
    int bid = blockIdx.x;
    if (bid < BB) {
        int b = bid, t = threadIdx.x;
        for (int idx = t; idx < NH * TT * 3; idx += blockDim.x) {
            int p = idx % 3; int ht = idx / 3; int h = ht / TT, tt = ht % TT;
            float s = 0.f;
            for (int d = 0; d < HD; d++)
                s += d_A[(h * HD + d) * 3 + p] * d_K2[(b * TT + tt) * EMB + h * HD + d];
            d_U[b * NH * TT * 3 + idx] = 0.25f * s;
        }
        for (int idx = t; idx < NH * TT; idx += blockDim.x) {
            int h = idx / TT, tt = idx % TT;
            float s = 0.f;
            for (int d = 0; d < HD; d++)
                s += d_cc[h * HD + d] * d_K2[(b * TT + tt) * EMB + h * HD + d];
            d_s0[b * NH * TT + idx] = 0.25f * s;
        }
        for (int idx = t; idx < NH * TT * EMB; idx += blockDim.x) {
            int j = idx % EMB; int ht = idx / EMB; int h = ht / TT, tt = ht % TT;
            float s = 0.f;
            for (int d = 0; d < HD; d++)
                s += out_w[j * EMB + h * HD + d] * d_V2[(b * TT + tt) * EMB + h * HD + d];
            d_OV[b * NH * TT * EMB + idx] = s;
        }
        return;
    }
    int m = (bid - BB) * 128 + threadIdx.x;
    int b = m / MPG;
    const float* cp = pos + (size_t)b * NPG * 3;
    for (int j = threadIdx.x; j < NPG; j += 128) {
        float X = cp[j * 3], Y = cp[j * 3 + 1], Z = cp[j * 3 + 2];
        sh4[j] = make_float4(X, Y, Z, -0.5f * (X * X + Y * Y + Z * Z));
    }
    __syncthreads();
    d_cnt[m] = 0;
    float4 z4 = make_float4(0.f, 0.f, 0.f, 0.f);
    #pragma unroll
    for (int q = 0; q < CI / 4; q++) ((float4*)(d_aggr + (size_t)m * CI))[q] = z4;

    float px = pos_skip[m * 3], py = pos_skip[m * 3 + 1], pz = pos_skip[m * 3 + 2];
    float ps2 = px * px + py * py + pz * pz;
    float b0 = -1e30f, b1 = -1e30f, b2 = -1e30f;
    int i0 = 0, i1 = 0, i2 = 0;
    #pragma unroll 4
    for (int j = 0; j < NPG; j++) {
        float4 c = sh4[j];
        float s = fmaf(px, c.x, fmaf(py, c.y, fmaf(pz, c.z, c.w)));
        if (s > b2) {
            if (s > b1) {
                b2 = b1; i2 = i1;
                if (s > b0) { b1 = b0; i1 = i0; b0 = s; i0 = j; }
                else        { b1 = s;  i1 = j; }
            } else { b2 = s; i2 = j; }
        }
    }
    float d0 = fmaf(-2.f, b0, ps2);
    float d1 = fmaf(-2.f, b1, ps2);
    float d2 = fmaf(-2.f, b2, ps2);
    float w0 = 1.f / fmaxf(d0, 1e-16f);
    float w1 = 1.f / fmaxf(d1, 1e-16f);
    float w2 = 1.f / fmaxf(d2, 1e-16f);
    float inv = 1.f / (w0 + w1 + w2);
    const float* x0 = x + (size_t)(b * NPG + i0) * FIN;
    const float* x1 = x + (size_t)(b * NPG + i1) * FIN;
    const float* x2 = x + (size_t)(b * NPG + i2) * FIN;
    const float* xs = x_skip + (size_t)m * FIN;
    float* h = d_h0 + (size_t)m * CI;
    #pragma unroll
    for (int f = 0; f < FIN; f++) {
        h[f]       = (w0 * x0[f] + w1 * x1[f] + w2 * x2[f]) * inv;
        h[FIN + f] = xs[f];
    }
}

__global__ void deg_kernel(const int* __restrict__ ei) {
    int e = blockIdx.x * blockDim.x + threadIdx.x;
    if (e < EE) atomicAdd(&d_cnt[ei[EE + e]], 1);
}

// ---------------- attention -> pseudo (row-major, stride 68) ----------------
__global__ void attn_kernel(const int* __restrict__ ei, const float* __restrict__ pos_skip,
                            const float* __restrict__ out_b) {
    __shared__ float4 sOV4[NH * TT * EMB / 4];
    __shared__ float sU[NH * TT * 3], sS0[NH * TT], sOB[EMB];
    int e = blockIdx.x * blockDim.x + threadIdx.x;
    int b = blockIdx.x / (EPG / 256);
    float* sOV = (float*)sOV4;
    for (int i = threadIdx.x; i < NH * TT * EMB; i += 256) sOV[i] = d_OV[b * NH * TT * EMB + i];
    for (int i = threadIdx.x; i < NH * TT * 3;  i += 256) sU[i]  = d_U[b * NH * TT * 3 + i];
    for (int i = threadIdx.x; i < NH * TT;      i += 256) sS0[i] = d_s0[b * NH * TT + i];
    for (int i = threadIdx.x; i < EMB;          i += 256) sOB[i] = out_b[i];
    __syncthreads();
    int s = ei[e], d = ei[EE + e];
    float sx = pos_skip[s * 3], sy = pos_skip[s * 3 + 1], sz = pos_skip[s * 3 + 2];
    float dx = pos_skip[d * 3], dy = pos_skip[d * 3 + 1], dz = pos_skip[d * 3 + 2];
    float epx = 0.5f * (dx + sx), epy = 0.5f * (dy + sy), epz = 0.5f * (dz + sz);
    float o[EMB];
    #pragma unroll
    for (int j = 0; j < EMB; j++) o[j] = sOB[j];
    #pragma unroll
    for (int h = 0; h < NH; h++) {
        float sc[TT];
        float mx = -1e30f;
        #pragma unroll
        for (int t = 0; t < TT; t++) {
            int ht = h * TT + t;
            sc[t] = sS0[ht] + epx * sU[ht * 3] + epy * sU[ht * 3 + 1] + epz * sU[ht * 3 + 2];
            mx = fmaxf(mx, sc[t]);
        }
        float se = 0.f;
        #pragma unroll
        for (int t = 0; t < TT; t++) { sc[t] = __expf(sc[t] - mx); se += sc[t]; }
        float inv = 1.f / se;
        #pragma unroll
        for (int t = 0; t < TT; t++) {
            float a = sc[t] * inv;
            const float4* row = sOV4 + (h * TT + t) * (EMB / 4);
            #pragma unroll
            for (int q = 0; q < EMB / 4; q++) {
                float4 vv = row[q];
                o[4 * q]     += a * vv.x;
                o[4 * q + 1] += a * vv.y;
                o[4 * q + 2] += a * vv.z;
                o[4 * q + 3] += a * vv.w;
            }
        }
    }
    float* pd = d_pseudo + (size_t)e * PROW;
    pd[0] = dx - sx; pd[1] = dy - sy; pd[2] = dz - sz;
    #pragma unroll
    for (int j = 0; j < EMB; j++) pd[3 + j] = o[j];
    pd[67] = 0.f;
}

// ---------------- stage C: HMMA (mma.sync bf16 split-K) edge MLP ----------------
template <int CO>
__global__ void __launch_bounds__(256)
edge_hmma_kernel(int layer, const int* __restrict__ ei, const float* __restrict__ nbias) {
    constexpr int NCH = (CO == 32) ? 8 : 4;   // 128-col chunks over J = 32*CO
    constexpr int NG  = (CO == 32) ? 4 : 2;   // o-groups per chunk
    extern __shared__ __align__(16) unsigned char dsm[];
    __shared__ float hs_s[128 * 33];
    __shared__ int   dst_s[128];
    __shared__ float nb_s[128];

    unsigned char* Asm = dsm;                 // 128 x ASTR
    unsigned char* Bsm = dsm + 128 * ASTR;    // 128 x ASTR
    u32 A_u = smem_u32(Asm), B_u = smem_u32(Bsm);

    const __nv_bfloat16* Bw = (layer == 0) ? d_Bw0 : (layer == 1) ? d_Bw1 : d_Bw2;
    const float* hin = (layer == 1) ? d_h1 : d_h0;
    int tid = threadIdx.x, l = tid & 31, wid = tid >> 5;
    int e0 = blockIdx.x * 128;

    // zero A tile
    {
        float4 z4 = make_float4(0.f, 0.f, 0.f, 0.f);
        for (int i = tid; i < 128 * ASTR / 16; i += 256) ((float4*)Asm)[i] = z4;
    }
    __syncthreads();

    // fill A (threads 0-127, one edge row each) + hs/dst (threads 128-255)
    if (tid < 128) {
        int r = tid;
        const float* pr = d_pseudo + (size_t)(e0 + r) * PROW;
        u32 rb = (u32)r * ASTR;
        #pragma unroll 2
        for (int c2 = 0; c2 < 34; c2++) {
            float v0 = pr[2 * c2], v1 = pr[2 * c2 + 1];
            __nv_bfloat16 h0 = __float2bfloat16(v0), h1 = __float2bfloat16(v1);
            __nv_bfloat16 l0 = __float2bfloat16(v0 - __bfloat162float(h0));
            __nv_bfloat16 l1 = __float2bfloat16(v1 - __bfloat162float(h1));
            u32 hp = pack_bf16(h0, h1), lp = pack_bf16(l0, l1);
            *(u32*)(Asm + rb + 4 * c2)       = hp;   // seg0: k = 2c2
            *(u32*)(Asm + rb + 160 + 4 * c2) = lp;   // seg1: k = 80 + 2c2
            *(u32*)(Asm + rb + 320 + 4 * c2) = hp;   // seg2: k = 160 + 2c2
        }
    } else {
        int r = tid - 128;
        int src = ei[e0 + r];
        dst_s[r] = ei[EE + e0 + r];
        const float4* hr = (const float4*)(hin + (size_t)src * CI);
        #pragma unroll
        for (int q = 0; q < CI / 4; q++) {
            float4 t4 = hr[q];
            hs_s[r * 33 + 4 * q]     = t4.x;
            hs_s[r * 33 + 4 * q + 1] = t4.y;
            hs_s[r * 33 + 4 * q + 2] = t4.z;
            hs_s[r * 33 + 4 * q + 3] = t4.w;
        }
    }

    float msg[NG][4];
    #pragma unroll
    for (int g = 0; g < NG; g++)
        #pragma unroll
        for (int c = 0; c < 4; c++) msg[g][c] = 0.f;

    int erow = wid * 16 + (l >> 2);
    int c0 = 2 * (l & 3);

    #pragma unroll 1
    for (int nc = 0; nc < NCH; nc++) {
        __syncthreads();
        // load B chunk: 128 j-rows x 240 k bf16 (row stride ASTR in smem)
        {
            const __nv_bfloat16* bg = Bw + (size_t)(nc * 128) * KP;
            for (int i = tid; i < 128 * 30; i += 256) {
                int row = i / 30, off = i - row * 30;
                ((float4*)(Bsm + (u32)row * ASTR))[off] =
                    ((const float4*)(bg + (size_t)row * KP))[off];
            }
            if (tid < 128) nb_s[tid] = nbias[nc * 128 + tid];
        }
        __syncthreads();

        float D[16][4];
        #pragma unroll
        for (int nt = 0; nt < 16; nt++)
            #pragma unroll
            for (int c = 0; c < 4; c++) D[nt][c] = 0.f;

        u32 abase = A_u + (u32)(wid * 16 + (l & 15)) * ASTR + ((l >> 4) & 1) * 16;
        u32 bbase = B_u + (u32)(l & 7) * ASTR + ((l >> 3) & 1) * 16;

        #pragma unroll 1
        for (int kk = 0; kk < 15; kk++) {
            u32 a0, a1, a2, a3;
            ldsm_x4(a0, a1, a2, a3, abase + kk * 32);
            #pragma unroll
            for (int nt = 0; nt < 16; nt++) {
                u32 b0, b1;
                ldsm_x2(b0, b1, bbase + (u32)nt * 8 * ASTR + kk * 32);
                mma_bf16(D[nt], a0, a1, a2, a3, b0, b1);
            }
        }

        // epilogue: bias + relu + h-contraction into msg
        #pragma unroll
        for (int nt = 0; nt < 16; nt++) {
            int j0 = nc * 128 + nt * 8;
            int i_idx = j0 / CO;
            float hv0 = hs_s[erow * 33 + i_idx];
            float hv1 = hs_s[(erow + 8) * 33 + i_idx];
            int g = (CO == 32) ? (nt & 3) : (nt & 1);
            float nb0 = nb_s[nt * 8 + c0], nb1 = nb_s[nt * 8 + c0 + 1];
            msg[g][0] = fmaf(hv0, fmaxf(D[nt][0] + nb0, 0.f), msg[g][0]);
            msg[g][1] = fmaf(hv0, fmaxf(D[nt][1] + nb1, 0.f), msg[g][1]);
            msg[g][2] = fmaf(hv1, fmaxf(D[nt][2] + nb0, 0.f), msg[g][2]);
            msg[g][3] = fmaf(hv1, fmaxf(D[nt][3] + nb1, 0.f), msg[g][3]);
        }
    }

    // scatter: thread owns (erow, erow+8) x (c0, c0+1) x NG o-groups
    int dlo = dst_s[erow], dhi = dst_s[erow + 8];
    #pragma unroll
    for (int g = 0; g < NG; g++) {
        int o0 = g * 8 + c0;
        atomicAdd(&d_aggr[(size_t)dlo * CO + o0],     msg[g][0]);
        atomicAdd(&d_aggr[(size_t)dlo * CO + o0 + 1], msg[g][1]);
        atomicAdd(&d_aggr[(size_t)dhi * CO + o0],     msg[g][2]);
        atomicAdd(&d_aggr[(size_t)dhi * CO + o0 + 1], msg[g][3]);
    }
}

// ---------------- node update ----------------
template <int CO>
__global__ void node_kernel(int layer, const float* __restrict__ root,
                            const float* __restrict__ bias, float* __restrict__ finalout,
                            int out_size) {
    __shared__ float4 root4[CI * CO / 4];
    __shared__ float  bias_s[CO];
    for (int i = threadIdx.x; i < CI * CO / 4; i += blockDim.x) root4[i] = ((const float4*)root)[i];
    for (int i = threadIdx.x; i < CO; i += blockDim.x) bias_s[i] = bias[i];
    __syncthreads();

    const float* hin = (layer == 1) ? d_h1 : d_h0;
    int v = blockIdx.x * blockDim.x + threadIdx.x;
    float inv = 1.f / (float)max(d_cnt[v], 1);

    float4 acc[CO / 4];
    #pragma unroll
    for (int q = 0; q < CO / 4; q++) {
        float4 ag = ((const float4*)(d_aggr + (size_t)v * CO))[q];
        acc[q].x = bias_s[4 * q]     + ag.x * inv;
        acc[q].y = bias_s[4 * q + 1] + ag.y * inv;
        acc[q].z = bias_s[4 * q + 2] + ag.z * inv;
        acc[q].w = bias_s[4 * q + 3] + ag.w * inv;
    }
    if (layer < 2) {
        float4 z4 = make_float4(0.f, 0.f, 0.f, 0.f);
        #pragma unroll
        for (int q = 0; q < CI / 4; q++) ((float4*)(d_aggr + (size_t)v * CI))[q] = z4;
    }
    float hv[CI];
    #pragma unroll
    for (int q = 0; q < CI / 4; q++) {
        float4 t = ((const float4*)(hin + (size_t)v * CI))[q];
        hv[4 * q] = t.x; hv[4 * q + 1] = t.y; hv[4 * q + 2] = t.z; hv[4 * q + 3] = t.w;
    }
    #pragma unroll
    for (int i = 0; i < CI; i++) {
        #pragma unroll
        for (int q = 0; q < CO / 4; q++) {
            float4 r = root4[i * (CO / 4) + q];
            acc[q].x = fmaf(hv[i], r.x, acc[q].x);
            acc[q].y = fmaf(hv[i], r.y, acc[q].y);
            acc[q].z = fmaf(hv[i], r.z, acc[q].z);
            acc[q].w = fmaf(hv[i], r.w, acc[q].w);
        }
    }
    float* hout = (layer == 0) ? d_h1 : (layer == 1) ? d_h0 : finalout;
    #pragma unroll
    for (int q = 0; q < CO / 4; q++) {
        float4 r;
        r.x = fmaxf(acc[q].x, 0.f); r.y = fmaxf(acc[q].y, 0.f);
        r.z = fmaxf(acc[q].z, 0.f); r.w = fmaxf(acc[q].w, 0.f);
        if (layer == 2) {
            int ofs = v * CO + 4 * q;
            if (ofs + 4 <= out_size) ((float4*)(hout + ofs))[0] = r;
        } else {
            ((float4*)(hout + (size_t)v * CO))[q] = r;
        }
    }
}

__global__ void tail_kernel(const float* __restrict__ pos_skip, const int* __restrict__ batch_skip,
                            float* __restrict__ out, int out_size) {
    int i = blockIdx.x * blockDim.x + threadIdx.x;
    int base = MM * 16;
    if (i < MM * 3 && base + i < out_size) out[base + i] = pos_skip[i];
    int base2 = base + MM * 3;
    if (i < MM && base2 + i < out_size) out[base2 + i] = (float)batch_skip[i];
}

// ---------------- launch ----------------
extern "C" void kernel_launch(void* const* d_in, const int* in_sizes, int n_in,
                              void* d_out, int out_size) {
    const float* x        = (const float*)d_in[0];
    const float* pos      = (const float*)d_in[1];
    const float* x_skip   = (const float*)d_in[3];
    const float* pos_skip = (const float*)d_in[4];
    const int*   batch_sk = (const int*)  d_in[5];
    const int*   ei       = (const int*)  d_in[6];
    const float* gt       = (const float*)d_in[7];
    const float* Wq_w = (const float*)d_in[8];   const float* Wq_b = (const float*)d_in[9];
    const float* Wk_w = (const float*)d_in[10];  const float* Wk_b = (const float*)d_in[11];
    const float* Wv_w = (const float*)d_in[12];  const float* Wv_b = (const float*)d_in[13];
    const float* ipw  = (const float*)d_in[14];  const float* ipb  = (const float*)d_in[15];
    const float* ow   = (const float*)d_in[16];  const float* ob   = (const float*)d_in[17];
    const float* nw0 = (const float*)d_in[18]; const float* nb0 = (const float*)d_in[19];
    const float* rt0 = (const float*)d_in[20]; const float* bs0 = (const float*)d_in[21];
    const float* nw1 = (const float*)d_in[22]; const float* nb1 = (const float*)d_in[23];
    const float* rt1 = (const float*)d_in[24]; const float* bs1 = (const float*)d_in[25];
    const float* nw2 = (const float*)d_in[26]; const float* nb2 = (const float*)d_in[27];
    const float* rt2 = (const float*)d_in[28]; const float* bs2 = (const float*)d_in[29];
    float* out = (float*)d_out;

    const int DSM = 2 * 128 * ASTR;   // A + B tiles = 126976 B
    cudaFuncSetAttribute(edge_hmma_kernel<32>, cudaFuncAttributeMaxDynamicSharedMemorySize, DSM);
    cudaFuncSetAttribute(edge_hmma_kernel<16>, cudaFuncAttributeMaxDynamicSharedMemorySize, DSM);

    setup_kernel<<<BB * TT + 1 + BWBLK, 256>>>(gt, Wk_w, Wk_b, Wv_w, Wv_b, ipw, ipb,
                                               Wq_w, Wq_b, nw0, nw1, nw2);
    mid_kernel<<<BB + MM / 128, 128>>>(x, pos, x_skip, pos_skip, ow);
    attn_kernel<<<EE / 256, 256>>>(ei, pos_skip, ob);

    edge_hmma_kernel<32><<<EE / 128, 256, DSM>>>(0, ei, nb0);   // launch #4 (profiled)
    deg_kernel<<<EE / 256, 256>>>(ei);
    node_kernel<32><<<MM / 256, 256>>>(0, rt0, bs0, nullptr, 0);
    edge_hmma_kernel<32><<<EE / 128, 256, DSM>>>(1, ei, nb1);
    node_kernel<32><<<MM / 256, 256>>>(1, rt1, bs1, nullptr, 0);
    edge_hmma_kernel<16><<<EE / 128, 256, DSM>>>(2, ei, nb2);
    node_kernel<16><<<MM / 256, 256>>>(2, rt2, bs2, out, out_size);

    tail_kernel<<<(MM * 3 + 255) / 256, 256>>>(pos_skip, batch_sk, out, out_size);
}

// round 16
// speedup vs baseline: 2.0003x; 1.1086x over previous
#include <cuda_runtime.h>
#include <cuda_bf16.h>

// ---------------- problem constants ----------------
#define BB   4
#define NPG  2048
#define MM   65536
#define MPG  16384
#define EE   131072
#define EPG  32768
#define TT   16
#define FIN  16
#define GDIM 1024
#define EMB  64
#define NH   4
#define HD   16
#define CI   32
#define PDIM 67
#define PROW 68          // pseudo row stride (floats)
#define KP   240         // split-K (3 x 80)
#define ASTR 496         // smem row stride bytes (conflict-free for ldmatrix)
#define BSZ  (128 * ASTR) // one tile buffer: 63488 B

typedef unsigned long long ull;
typedef unsigned int u32;

__device__ __forceinline__ u32 smem_u32(const void* p) {
    u32 a;
    asm("{ .reg .u64 t; cvta.to.shared.u64 t, %1; cvt.u32.u64 %0, t; }" : "=r"(a) : "l"(p));
    return a;
}
__device__ __forceinline__ void ldsm_x4(u32& r0, u32& r1, u32& r2, u32& r3, u32 a) {
    asm volatile("ldmatrix.sync.aligned.m8n8.x4.shared.b16 {%0,%1,%2,%3}, [%4];"
        : "=r"(r0), "=r"(r1), "=r"(r2), "=r"(r3) : "r"(a));
}
__device__ __forceinline__ void mma_bf16(float* d, u32 a0, u32 a1, u32 a2, u32 a3, u32 b0, u32 b1) {
    asm volatile("mma.sync.aligned.m16n8k16.row.col.f32.bf16.bf16.f32 "
        "{%0,%1,%2,%3}, {%4,%5,%6,%7}, {%8,%9}, {%0,%1,%2,%3};"
        : "+f"(d[0]), "+f"(d[1]), "+f"(d[2]), "+f"(d[3])
        : "r"(a0), "r"(a1), "r"(a2), "r"(a3), "r"(b0), "r"(b1));
}
__device__ __forceinline__ u32 pack_bf16(__nv_bfloat16 lo, __nv_bfloat16 hi) {
    return ((u32)__bfloat16_as_ushort(hi) << 16) | (u32)__bfloat16_as_ushort(lo);
}
__device__ __forceinline__ void cp_async16(u32 dst, const void* src) {
    asm volatile("cp.async.cg.shared.global [%0], [%1], 16;" :: "r"(dst), "l"(src));
}
#define CP_COMMIT() asm volatile("cp.async.commit_group;" ::: "memory")
#define CP_WAIT0()  asm volatile("cp.async.wait_group 0;" ::: "memory")

// ---------------- device scratch ----------------
__device__ __align__(16) float d_pseudo[EE * PROW];
__device__ float d_h0[MM * CI];
__device__ float d_h1[MM * CI];
__device__ float d_aggr[MM * CI];
__device__ int   d_cnt[MM];
// bf16 split-K weight images: [j][240], j-major, k contiguous
__device__ __align__(16) __nv_bfloat16 d_Bw0[1024 * KP];
__device__ __align__(16) __nv_bfloat16 d_Bw1[1024 * KP];
__device__ __align__(16) __nv_bfloat16 d_Bw2[512 * KP];
__device__ float d_A[EMB * 3];
__device__ float d_cc[EMB];
__device__ float d_K2[BB * TT * EMB];
__device__ float d_V2[BB * TT * EMB];
__device__ float d_U[BB * NH * TT * 3];
__device__ float d_s0[BB * NH * TT];
__device__ float d_OV[BB * NH * TT * EMB];

// ---------------- setup: tokens + A/cc + B weight images ----------------
#define BWTOT ((1024 + 1024 + 512) * KP)    // 614400
#define BWBLK (BWTOT / 256)                 // 2400

__global__ void setup_kernel(const float* __restrict__ gt,
                             const float* __restrict__ Wk_w, const float* __restrict__ Wk_b,
                             const float* __restrict__ Wv_w, const float* __restrict__ Wv_b,
                             const float* __restrict__ ipw, const float* __restrict__ ipb,
                             const float* __restrict__ Wq_w, const float* __restrict__ Wq_b,
                             const float* __restrict__ nw0, const float* __restrict__ nw1,
                             const float* __restrict__ nw2) {
    int bid = blockIdx.x;
    if (bid < BB * TT) {
        __shared__ float pK[4][EMB], pV[4][EMB];
        __shared__ float Kt[EMB], Vt[EMB];
        int bt = bid, tloc = bt % TT;
        int q = threadIdx.x >> 6, j = threadIdx.x & 63;
        const float* g  = gt + (size_t)bt * GDIM + q * 256;
        const float* wk = Wk_w + (size_t)j * GDIM + q * 256;
        const float* wv = Wv_w + (size_t)j * GDIM + q * 256;
        float sk = 0.f, sv = 0.f;
        for (int i = 0; i < 256; i += 4) {
            float4 gv = *(const float4*)(g + i);
            float4 k4 = *(const float4*)(wk + i);
            float4 v4 = *(const float4*)(wv + i);
            sk += gv.x * k4.x + gv.y * k4.y + gv.z * k4.z + gv.w * k4.w;
            sv += gv.x * v4.x + gv.y * v4.y + gv.z * v4.z + gv.w * v4.w;
        }
        pK[q][j] = sk; pV[q][j] = sv;
        __syncthreads();
        if (q == 0) {
            int i2 = j & ~1;
            float div = expf(-(float)i2 * (9.210340371976184f / (float)EMB));
            float ang = (float)tloc * div;
            float pe = (j & 1) ? cosf(ang) : sinf(ang);
            Kt[j] = pK[0][j] + pK[1][j] + pK[2][j] + pK[3][j] + Wk_b[j] + pe;
            Vt[j] = pV[0][j] + pV[1][j] + pV[2][j] + pV[3][j] + Wv_b[j] + pe;
        }
        __syncthreads();
        if (q == 0) {
            const float* wkr = ipw + (size_t)(EMB + j) * EMB;
            const float* wvr = ipw + (size_t)(2 * EMB + j) * EMB;
            float s2k = ipb[EMB + j], s2v = ipb[2 * EMB + j];
            for (int i = 0; i < EMB; i++) { s2k += Kt[i] * wkr[i]; s2v += Vt[i] * wvr[i]; }
            d_K2[bt * EMB + j] = s2k;
            d_V2[bt * EMB + j] = s2v;
        }
        return;
    }
    if (bid == BB * TT) {
        int t = threadIdx.x;
        for (int idx = t; idx < EMB * 3; idx += blockDim.x) {
            int j = idx / 3, p = idx % 3;
            float s = 0.f;
            for (int i = 0; i < EMB; i++) s += ipw[j * EMB + i] * Wq_w[i * 3 + p];
            d_A[idx] = s;
        }
        for (int j = t; j < EMB; j += blockDim.x) {
            float s = ipb[j];
            for (int i = 0; i < EMB; i++) s += ipw[j * EMB + i] * Wq_b[i];
            d_cc[j] = s;
        }
        return;
    }
    // B image: k<80 -> hi, 80..159 -> hi, 160..239 -> lo
    int u = (bid - (BB * TT + 1)) * 256 + threadIdx.x;
    const float* nw; __nv_bfloat16* Bw; int rel;
    if (u < 1024 * KP)            { nw = nw0; Bw = d_Bw0; rel = u; }
    else if (u < 2048 * KP)       { nw = nw1; Bw = d_Bw1; rel = u - 1024 * KP; }
    else if (u < 2560 * KP)       { nw = nw2; Bw = d_Bw2; rel = u - 2048 * KP; }
    else return;
    int j = rel / KP, k = rel - j * KP;
    int seg = k / 80, c = k - seg * 80;
    float w = (c < PDIM) ? nw[j * PDIM + c] : 0.f;
    __nv_bfloat16 hi = __float2bfloat16(w);
    __nv_bfloat16 lo = __float2bfloat16(w - __bfloat162float(hi));
    Bw[rel] = (seg == 2) ? lo : hi;
}

// ---------------- mid: s3 (blocks 0..3) + knn (rest) ----------------
__global__ void mid_kernel(const float* __restrict__ x, const float* __restrict__ pos,
                           const float* __restrict__ x_skip, const float* __restrict__ pos_skip,
                           const float* __restrict__ out_w) {
    __shared__ __align__(16) float4 sh4[NPG];
    int bid = blockIdx.x;
    if (bid < BB) {
        int b = bid, t = threadIdx.x;
        for (int idx = t; idx < NH * TT * 3; idx += blockDim.x) {
            int p = idx % 3; int ht = idx / 3; int h = ht / TT, tt = ht % TT;
            float s = 0.f;
            for (int d = 0; d < HD; d++)
                s += d_A[(h * HD + d) * 3 + p] * d_K2[(b * TT + tt) * EMB + h * HD + d];
            d_U[b * NH * TT * 3 + idx] = 0.25f * s;
        }
        for (int idx = t; idx < NH * TT; idx += blockDim.x) {
            int h = idx / TT, tt = idx % TT;
            float s = 0.f;
            for (int d = 0; d < HD; d++)
                s += d_cc[h * HD + d] * d_K2[(b * TT + tt) * EMB + h * HD + d];
            d_s0[b * NH * TT + idx] = 0.25f * s;
        }
        for (int idx = t; idx < NH * TT * EMB; idx += blockDim.x) {
            int j = idx % EMB; int ht = idx / EMB; int h = ht / TT, tt = ht % TT;
            float s = 0.f;
            for (int d = 0; d < HD; d++)
                s += out_w[j * EMB + h * HD + d] * d_V2[(b * TT + tt) * EMB + h * HD + d];
            d_OV[b * NH * TT * EMB + idx] = s;
        }
        return;
    }
    int m = (bid - BB) * 128 + threadIdx.x;
    int b = m / MPG;
    const float* cp = pos + (size_t)b * NPG * 3;
    for (int j = threadIdx.x; j < NPG; j += 128) {
        float X = cp[j * 3], Y = cp[j * 3 + 1], Z = cp[j * 3 + 2];
        sh4[j] = make_float4(X, Y, Z, -0.5f * (X * X + Y * Y + Z * Z));
    }
    __syncthreads();
    d_cnt[m] = 0;
    float4 z4 = make_float4(0.f, 0.f, 0.f, 0.f);
    #pragma unroll
    for (int q = 0; q < CI / 4; q++) ((float4*)(d_aggr + (size_t)m * CI))[q] = z4;

    float px = pos_skip[m * 3], py = pos_skip[m * 3 + 1], pz = pos_skip[m * 3 + 2];
    float ps2 = px * px + py * py + pz * pz;
    float b0 = -1e30f, b1 = -1e30f, b2 = -1e30f;
    int i0 = 0, i1 = 0, i2 = 0;
    #pragma unroll 4
    for (int j = 0; j < NPG; j++) {
        float4 c = sh4[j];
        float s = fmaf(px, c.x, fmaf(py, c.y, fmaf(pz, c.z, c.w)));
        if (s > b2) {
            if (s > b1) {
                b2 = b1; i2 = i1;
                if (s > b0) { b1 = b0; i1 = i0; b0 = s; i0 = j; }
                else        { b1 = s;  i1 = j; }
            } else { b2 = s; i2 = j; }
        }
    }
    float d0 = fmaf(-2.f, b0, ps2);
    float d1 = fmaf(-2.f, b1, ps2);
    float d2 = fmaf(-2.f, b2, ps2);
    float w0 = 1.f / fmaxf(d0, 1e-16f);
    float w1 = 1.f / fmaxf(d1, 1e-16f);
    float w2 = 1.f / fmaxf(d2, 1e-16f);
    float inv = 1.f / (w0 + w1 + w2);
    const float* x0 = x + (size_t)(b * NPG + i0) * FIN;
    const float* x1 = x + (size_t)(b * NPG + i1) * FIN;
    const float* x2 = x + (size_t)(b * NPG + i2) * FIN;
    const float* xs = x_skip + (size_t)m * FIN;
    float* h = d_h0 + (size_t)m * CI;
    #pragma unroll
    for (int f = 0; f < FIN; f++) {
        h[f]       = (w0 * x0[f] + w1 * x1[f] + w2 * x2[f]) * inv;
        h[FIN + f] = xs[f];
    }
}

__global__ void deg_kernel(const int* __restrict__ ei) {
    int e = blockIdx.x * blockDim.x + threadIdx.x;
    if (e < EE) atomicAdd(&d_cnt[ei[EE + e]], 1);
}

// ---------------- attention -> pseudo (row-major, stride 68) ----------------
__global__ void attn_kernel(const int* __restrict__ ei, const float* __restrict__ pos_skip,
                            const float* __restrict__ out_b) {
    __shared__ float4 sOV4[NH * TT * EMB / 4];
    __shared__ float sU[NH * TT * 3], sS0[NH * TT], sOB[EMB];
    int e = blockIdx.x * blockDim.x + threadIdx.x;
    int b = blockIdx.x / (EPG / 256);
    float* sOV = (float*)sOV4;
    for (int i = threadIdx.x; i < NH * TT * EMB; i += 256) sOV[i] = d_OV[b * NH * TT * EMB + i];
    for (int i = threadIdx.x; i < NH * TT * 3;  i += 256) sU[i]  = d_U[b * NH * TT * 3 + i];
    for (int i = threadIdx.x; i < NH * TT;      i += 256) sS0[i] = d_s0[b * NH * TT + i];
    for (int i = threadIdx.x; i < EMB;          i += 256) sOB[i] = out_b[i];
    __syncthreads();
    int s = ei[e], d = ei[EE + e];
    float sx = pos_skip[s * 3], sy = pos_skip[s * 3 + 1], sz = pos_skip[s * 3 + 2];
    float dx = pos_skip[d * 3], dy = pos_skip[d * 3 + 1], dz = pos_skip[d * 3 + 2];
    float epx = 0.5f * (dx + sx), epy = 0.5f * (dy + sy), epz = 0.5f * (dz + sz);
    float o[EMB];
    #pragma unroll
    for (int j = 0; j < EMB; j++) o[j] = sOB[j];
    #pragma unroll
    for (int h = 0; h < NH; h++) {
        float sc[TT];
        float mx = -1e30f;
        #pragma unroll
        for (int t = 0; t < TT; t++) {
            int ht = h * TT + t;
            sc[t] = sS0[ht] + epx * sU[ht * 3] + epy * sU[ht * 3 + 1] + epz * sU[ht * 3 + 2];
            mx = fmaxf(mx, sc[t]);
        }
        float se = 0.f;
        #pragma unroll
        for (int t = 0; t < TT; t++) { sc[t] = __expf(sc[t] - mx); se += sc[t]; }
        float inv = 1.f / se;
        #pragma unroll
        for (int t = 0; t < TT; t++) {
            float a = sc[t] * inv;
            const float4* row = sOV4 + (h * TT + t) * (EMB / 4);
            #pragma unroll
            for (int q = 0; q < EMB / 4; q++) {
                float4 vv = row[q];
                o[4 * q]     += a * vv.x;
                o[4 * q + 1] += a * vv.y;
                o[4 * q + 2] += a * vv.z;
                o[4 * q + 3] += a * vv.w;
            }
        }
    }
    float* pd = d_pseudo + (size_t)e * PROW;
    pd[0] = dx - sx; pd[1] = dy - sy; pd[2] = dz - sz;
    #pragma unroll
    for (int j = 0; j < EMB; j++) pd[3 + j] = o[j];
    pd[67] = 0.f;
}

// ---------------- stage C: HMMA edge MLP (x4 B ldmatrix, cp.async double-buffered B) ----------------
template <int CO>
__global__ void __launch_bounds__(256)
edge_hmma_kernel(int layer, const int* __restrict__ ei, const float* __restrict__ nbias) {
    constexpr int NCH = (CO == 32) ? 8 : 4;   // 128-col chunks over J = 32*CO
    constexpr int NG  = (CO == 32) ? 4 : 2;   // o-groups per chunk
    extern __shared__ __align__(16) unsigned char dsm[];
    __shared__ float hs_s[128 * 33];
    __shared__ int   dst_s[128];
    __shared__ float nb_s[2][128];

    unsigned char* Asm = dsm;                    // 128 x ASTR
    u32 A_u = smem_u32(Asm);
    u32 B_u = A_u + BSZ;                         // 2 buffers of BSZ

    const __nv_bfloat16* Bw = (layer == 0) ? d_Bw0 : (layer == 1) ? d_Bw1 : d_Bw2;
    const float* hin = (layer == 1) ? d_h1 : d_h0;
    int tid = threadIdx.x, l = tid & 31, wid = tid >> 5;
    int e0 = blockIdx.x * 128;

    // stage B chunk 0 (async) first so it overlaps the A build
    {
        const __nv_bfloat16* bg = Bw;
        for (int i = tid; i < 128 * 30; i += 256) {
            int row = i / 30, off = i - row * 30;
            cp_async16(B_u + (u32)row * ASTR + off * 16, bg + (size_t)row * KP + off * 8);
        }
        CP_COMMIT();
        if (tid < 128) nb_s[0][tid] = nbias[tid];
    }

    // fill A (threads 0-127, one edge row each) + hs/dst (threads 128-255)
    if (tid < 128) {
        int r = tid;
        const float* pr = d_pseudo + (size_t)(e0 + r) * PROW;
        u32 rb = A_u + (u32)r * ASTR;
        #pragma unroll 2
        for (int c2 = 0; c2 < 34; c2++) {
            float v0 = pr[2 * c2], v1 = pr[2 * c2 + 1];
            __nv_bfloat16 h0 = __float2bfloat16(v0), h1 = __float2bfloat16(v1);
            __nv_bfloat16 l0 = __float2bfloat16(v0 - __bfloat162float(h0));
            __nv_bfloat16 l1 = __float2bfloat16(v1 - __bfloat162float(h1));
            u32 hp = pack_bf16(h0, h1), lp = pack_bf16(l0, l1);
            asm volatile("st.shared.b32 [%0], %1;" :: "r"(rb + 4 * c2), "r"(hp) : "memory");
            asm volatile("st.shared.b32 [%0], %1;" :: "r"(rb + 160 + 4 * c2), "r"(lp) : "memory");
            asm volatile("st.shared.b32 [%0], %1;" :: "r"(rb + 320 + 4 * c2), "r"(hp) : "memory");
        }
        // zero the k-padding gaps [136,160) [296,320) [456,496)
        #pragma unroll
        for (int gp = 0; gp < 6; gp++) {
            asm volatile("st.shared.b32 [%0], %1;" :: "r"(rb + 136 + 4 * gp), "r"(0u) : "memory");
            asm volatile("st.shared.b32 [%0], %1;" :: "r"(rb + 296 + 4 * gp), "r"(0u) : "memory");
        }
        #pragma unroll
        for (int gp = 0; gp < 10; gp++)
            asm volatile("st.shared.b32 [%0], %1;" :: "r"(rb + 456 + 4 * gp), "r"(0u) : "memory");
    } else {
        int r = tid - 128;
        int src = ei[e0 + r];
        dst_s[r] = ei[EE + e0 + r];
        const float4* hr = (const float4*)(hin + (size_t)src * CI);
        #pragma unroll
        for (int q = 0; q < CI / 4; q++) {
            float4 t4 = hr[q];
            hs_s[r * 33 + 4 * q]     = t4.x;
            hs_s[r * 33 + 4 * q + 1] = t4.y;
            hs_s[r * 33 + 4 * q + 2] = t4.z;
            hs_s[r * 33 + 4 * q + 3] = t4.w;
        }
    }
    CP_WAIT0();
    __syncthreads();

    float msg[NG][4];
    #pragma unroll
    for (int g = 0; g < NG; g++)
        #pragma unroll
        for (int c = 0; c < 4; c++) msg[g][c] = 0.f;

    int erow = wid * 16 + (l >> 2);
    int c0 = 2 * (l & 3);
    u32 abase = A_u + (u32)(wid * 16 + (l & 15)) * ASTR + ((l >> 4) & 1) * 16;
    u32 boff  = (u32)(l & 7) * ASTR + ((l >> 3) & 1) * 16 + ((l >> 4) & 1) * 8 * ASTR;

    #pragma unroll 1
    for (int nc = 0; nc < NCH; nc++) {
        int cur = nc & 1, nxt = 1 - cur;
        // prefetch next B chunk while computing this one
        if (nc + 1 < NCH) {
            const __nv_bfloat16* bg = Bw + (size_t)((nc + 1) * 128) * KP;
            u32 bdst = B_u + (u32)nxt * BSZ;
            for (int i = tid; i < 128 * 30; i += 256) {
                int row = i / 30, off = i - row * 30;
                cp_async16(bdst + (u32)row * ASTR + off * 16, bg + (size_t)row * KP + off * 8);
            }
            CP_COMMIT();
            if (tid < 128) nb_s[nxt][tid] = nbias[(nc + 1) * 128 + tid];
        }

        float D[16][4];
        #pragma unroll
        for (int nt = 0; nt < 16; nt++)
            #pragma unroll
            for (int c = 0; c < 4; c++) D[nt][c] = 0.f;

        u32 bbase = B_u + (u32)cur * BSZ + boff;

        #pragma unroll 1
        for (int kk = 0; kk < 15; kk++) {
            u32 a0, a1, a2, a3;
            ldsm_x4(a0, a1, a2, a3, abase + kk * 32);
            #pragma unroll
            for (int ntp = 0; ntp < 8; ntp++) {
                u32 b0, b1, b2, b3;
                ldsm_x4(b0, b1, b2, b3, bbase + (u32)ntp * (16 * ASTR) + kk * 32);
                mma_bf16(D[2 * ntp],     a0, a1, a2, a3, b0, b1);
                mma_bf16(D[2 * ntp + 1], a0, a1, a2, a3, b2, b3);
            }
        }

        // epilogue: bias + relu + h-contraction into msg
        const float* nbv = nb_s[cur];
        #pragma unroll
        for (int nt = 0; nt < 16; nt++) {
            int j0 = nc * 128 + nt * 8;
            int i_idx = j0 / CO;
            float hv0 = hs_s[erow * 33 + i_idx];
            float hv1 = hs_s[(erow + 8) * 33 + i_idx];
            int g = (CO == 32) ? (nt & 3) : (nt & 1);
            float nb0 = nbv[nt * 8 + c0], nb1 = nbv[nt * 8 + c0 + 1];
            msg[g][0] = fmaf(hv0, fmaxf(D[nt][0] + nb0, 0.f), msg[g][0]);
            msg[g][1] = fmaf(hv0, fmaxf(D[nt][1] + nb1, 0.f), msg[g][1]);
            msg[g][2] = fmaf(hv1, fmaxf(D[nt][2] + nb0, 0.f), msg[g][2]);
            msg[g][3] = fmaf(hv1, fmaxf(D[nt][3] + nb1, 0.f), msg[g][3]);
        }
        CP_WAIT0();
        __syncthreads();
    }

    // scatter: thread owns (erow, erow+8) x (c0, c0+1) x NG o-groups
    int dlo = dst_s[erow], dhi = dst_s[erow + 8];
    #pragma unroll
    for (int g = 0; g < NG; g++) {
        int o0 = g * 8 + c0;
        atomicAdd(&d_aggr[(size_t)dlo * CO + o0],     msg[g][0]);
        atomicAdd(&d_aggr[(size_t)dlo * CO + o0 + 1], msg[g][1]);
        atomicAdd(&d_aggr[(size_t)dhi * CO + o0],     msg[g][2]);
        atomicAdd(&d_aggr[(size_t)dhi * CO + o0 + 1], msg[g][3]);
    }
}

// ---------------- node update ----------------
template <int CO>
__global__ void node_kernel(int layer, const float* __restrict__ root,
                            const float* __restrict__ bias, float* __restrict__ finalout,
                            int out_size) {
    __shared__ float4 root4[CI * CO / 4];
    __shared__ float  bias_s[CO];
    for (int i = threadIdx.x; i < CI * CO / 4; i += blockDim.x) root4[i] = ((const float4*)root)[i];
    for (int i = threadIdx.x; i < CO; i += blockDim.x) bias_s[i] = bias[i];
    __syncthreads();

    const float* hin = (layer == 1) ? d_h1 : d_h0;
    int v = blockIdx.x * blockDim.x + threadIdx.x;
    float inv = 1.f / (float)max(d_cnt[v], 1);

    float4 acc[CO / 4];
    #pragma unroll
    for (int q = 0; q < CO / 4; q++) {
        float4 ag = ((const float4*)(d_aggr + (size_t)v * CO))[q];
        acc[q].x = bias_s[4 * q]     + ag.x * inv;
        acc[q].y = bias_s[4 * q + 1] + ag.y * inv;
        acc[q].z = bias_s[4 * q + 2] + ag.z * inv;
        acc[q].w = bias_s[4 * q + 3] + ag.w * inv;
    }
    if (layer < 2) {
        float4 z4 = make_float4(0.f, 0.f, 0.f, 0.f);
        #pragma unroll
        for (int q = 0; q < CI / 4; q++) ((float4*)(d_aggr + (size_t)v * CI))[q] = z4;
    }
    float hv[CI];
    #pragma unroll
    for (int q = 0; q < CI / 4; q++) {
        float4 t = ((const float4*)(hin + (size_t)v * CI))[q];
        hv[4 * q] = t.x; hv[4 * q + 1] = t.y; hv[4 * q + 2] = t.z; hv[4 * q + 3] = t.w;
    }
    #pragma unroll
    for (int i = 0; i < CI; i++) {
        #pragma unroll
        for (int q = 0; q < CO / 4; q++) {
            float4 r = root4[i * (CO / 4) + q];
            acc[q].x = fmaf(hv[i], r.x, acc[q].x);
            acc[q].y = fmaf(hv[i], r.y, acc[q].y);
            acc[q].z = fmaf(hv[i], r.z, acc[q].z);
            acc[q].w = fmaf(hv[i], r.w, acc[q].w);
        }
    }
    float* hout = (layer == 0) ? d_h1 : (layer == 1) ? d_h0 : finalout;
    #pragma unroll
    for (int q = 0; q < CO / 4; q++) {
        float4 r;
        r.x = fmaxf(acc[q].x, 0.f); r.y = fmaxf(acc[q].y, 0.f);
        r.z = fmaxf(acc[q].z, 0.f); r.w = fmaxf(acc[q].w, 0.f);
        if (layer == 2) {
            int ofs = v * CO + 4 * q;
            if (ofs + 4 <= out_size) ((float4*)(hout + ofs))[0] = r;
        } else {
            ((float4*)(hout + (size_t)v * CO))[q] = r;
        }
    }
}

__global__ void tail_kernel(const float* __restrict__ pos_skip, const int* __restrict__ batch_skip,
                            float* __restrict__ out, int out_size) {
    int i = blockIdx.x * blockDim.x + threadIdx.x;
    int base = MM * 16;
    if (i < MM * 3 && base + i < out_size) out[base + i] = pos_skip[i];
    int base2 = base + MM * 3;
    if (i < MM && base2 + i < out_size) out[base2 + i] = (float)batch_skip[i];
}

// ---------------- launch ----------------
extern "C" void kernel_launch(void* const* d_in, const int* in_sizes, int n_in,
                              void* d_out, int out_size) {
    const float* x        = (const float*)d_in[0];
    const float* pos      = (const float*)d_in[1];
    const float* x_skip   = (const float*)d_in[3];
    const float* pos_skip = (const float*)d_in[4];
    const int*   batch_sk = (const int*)  d_in[5];
    const int*   ei       = (const int*)  d_in[6];
    const float* gt       = (const float*)d_in[7];
    const float* Wq_w = (const float*)d_in[8];   const float* Wq_b = (const float*)d_in[9];
    const float* Wk_w = (const float*)d_in[10];  const float* Wk_b = (const float*)d_in[11];
    const float* Wv_w = (const float*)d_in[12];  const float* Wv_b = (const float*)d_in[13];
    const float* ipw  = (const float*)d_in[14];  const float* ipb  = (const float*)d_in[15];
    const float* ow   = (const float*)d_in[16];  const float* ob   = (const float*)d_in[17];
    const float* nw0 = (const float*)d_in[18]; const float* nb0 = (const float*)d_in[19];
    const float* rt0 = (const float*)d_in[20]; const float* bs0 = (const float*)d_in[21];
    const float* nw1 = (const float*)d_in[22]; const float* nb1 = (const float*)d_in[23];
    const float* rt1 = (const float*)d_in[24]; const float* bs1 = (const float*)d_in[25];
    const float* nw2 = (const float*)d_in[26]; const float* nb2 = (const float*)d_in[27];
    const float* rt2 = (const float*)d_in[28]; const float* bs2 = (const float*)d_in[29];
    float* out = (float*)d_out;

    const int DSM = 3 * BSZ;   // A + 2x B = 190464 B
    cudaFuncSetAttribute(edge_hmma_kernel<32>, cudaFuncAttributeMaxDynamicSharedMemorySize, DSM);
    cudaFuncSetAttribute(edge_hmma_kernel<16>, cudaFuncAttributeMaxDynamicSharedMemorySize, DSM);

    setup_kernel<<<BB * TT + 1 + BWBLK, 256>>>(gt, Wk_w, Wk_b, Wv_w, Wv_b, ipw, ipb,
                                               Wq_w, Wq_b, nw0, nw1, nw2);
    mid_kernel<<<BB + MM / 128, 128>>>(x, pos, x_skip, pos_skip, ow);
    attn_kernel<<<EE / 256, 256>>>(ei, pos_skip, ob);

    edge_hmma_kernel<32><<<EE / 128, 256, DSM>>>(0, ei, nb0);   // launch #4 (profiled)
    deg_kernel<<<EE / 256, 256>>>(ei);
    node_kernel<32><<<MM / 256, 256>>>(0, rt0, bs0, nullptr, 0);
    edge_hmma_kernel<32><<<EE / 128, 256, DSM>>>(1, ei, nb1);
    node_kernel<32><<<MM / 256, 256>>>(1, rt1, bs1, nullptr, 0);
    edge_hmma_kernel<16><<<EE / 128, 256, DSM>>>(2, ei, nb2);
    node_kernel<16><<<MM / 256, 256>>>(2, rt2, bs2, out, out_size);

    tail_kernel<<<(MM * 3 + 255) / 256, 256>>>(pos_skip, batch_sk, out, out_size);
}